// round 9
// baseline (speedup 1.0000x reference)
#include <cuda_runtime.h>
#include <math.h>

#define HDIM 5000
#define IDIM 4000

// Intermediate hidden states + zero-detection flags (device globals)
__device__ float g_h1[HDIM];
__device__ float g_h2[HDIM];
__device__ int   g_nonzero[2];   // [0]: h_t nonzero, [1]: h2_t nonzero

__device__ __forceinline__ float warp_reduce(float v) {
    v += __shfl_down_sync(0xffffffffu, v, 16);
    v += __shfl_down_sync(0xffffffffu, v, 8);
    v += __shfl_down_sync(0xffffffffu, v, 4);
    v += __shfl_down_sync(0xffffffffu, v, 2);
    v += __shfl_down_sync(0xffffffffu, v, 1);
    return v;
}

__device__ __forceinline__ float sigmoidf_(float x) {
    return 1.0f / (1.0f + __expf(-x));
}

// Streaming (evict-first) float4 load for once-read weight data.
__device__ __forceinline__ float4 ldcs4(const float4* p) {
    return __ldcs(p);
}

// Prologue: detect whether each persistent hidden state is entirely zero.
// blockIdx.x = 0 -> h_t, 1 -> h2_t. float4 loads, 1024 threads.
__global__ __launch_bounds__(1024) void zero_flag_kernel(
    const float* __restrict__ ha, const float* __restrict__ hb)
{
    const float* __restrict__ v = (blockIdx.x == 0) ? ha : hb;
    const float4* __restrict__ v4 = (const float4*)v;
    int nz = 0;
    for (int i = threadIdx.x; i < HDIM / 4; i += 1024) {
        float4 a = v4[i];
        nz |= (a.x != 0.0f) | (a.y != 0.0f) | (a.z != 0.0f) | (a.w != 0.0f);
    }
    nz = __syncthreads_or(nz);
    if (threadIdx.x == 0) g_nonzero[blockIdx.x] = nz;
}

// One block per output element j (grid = HDIM). 4 warps; warp g computes the
// full dot product for gate-row g*HDIM + j over [x | h_prev], then thread 0
// applies the LSTM cell elementwise math. The W_hh stream is skipped entirely
// (uniform branch) when the prologue detected h_prev == 0.
// unroll 8 + ldcs: best measured config — DO NOT PERTURB (at ~80% HBM).
template <int NIN>
__global__ __launch_bounds__(128) void lstm_cell_kernel(
    const float* __restrict__ x,       // [NIN]
    const float* __restrict__ w_ih,    // [4H, NIN]
    const float* __restrict__ w_hh,    // [4H, H]
    const float* __restrict__ b_ih,    // [4H]
    const float* __restrict__ b_hh,    // [4H]
    const float* __restrict__ h_prev,  // [H]
    const float* __restrict__ c_prev,  // [H]
    float* __restrict__ h_out,         // [H]
    int flag_idx)
{
    const int j    = blockIdx.x;
    const int wrp  = threadIdx.x >> 5;   // gate index 0..3 (i, f, g, o)
    const int lane = threadIdx.x & 31;
    const int row  = wrp * HDIM + j;

    __shared__ float s_gate[4];

    float acc = 0.0f;

    // dot(W_ih[row, :], x)  — weights streamed (evict-first), x cached
    {
        const float4* __restrict__ wr = (const float4*)(w_ih + (size_t)row * NIN);
        const float4* __restrict__ xv = (const float4*)x;
        #pragma unroll 8
        for (int v = lane; v < NIN / 4; v += 32) {
            float4 a = ldcs4(wr + v);
            float4 b = xv[v];
            acc += a.x * b.x + a.y * b.y + a.z * b.z + a.w * b.w;
        }
    }

    // dot(W_hh[row, :], h_prev) — skipped when h_prev is all-zero.
    if (g_nonzero[flag_idx]) {
        const float4* __restrict__ wr = (const float4*)(w_hh + (size_t)row * HDIM);
        const float4* __restrict__ hv = (const float4*)h_prev;
        #pragma unroll 8
        for (int v = lane; v < HDIM / 4; v += 32) {
            float4 a = ldcs4(wr + v);
            float4 b = hv[v];
            acc += a.x * b.x + a.y * b.y + a.z * b.z + a.w * b.w;
        }
    }

    acc = warp_reduce(acc);
    if (lane == 0) {
        s_gate[wrp] = acc + b_ih[row] + b_hh[row];
    }
    __syncthreads();

    if (threadIdx.x == 0) {
        float gi = sigmoidf_(s_gate[0]);
        float gf = sigmoidf_(s_gate[1]);
        float gg = tanhf(s_gate[2]);
        float go = sigmoidf_(s_gate[3]);
        float c_new = gf * c_prev[j] + gi * gg;
        h_out[j] = go * tanhf(c_new);
    }
}

// out[r] = dot(W[r,:], h) + b[r].  One warp per row, 8 warps/block, grid=500.
// h is staged into shared memory once per block (removes all global h traffic
// from the hot loop); weights streamed with __ldcs; unroll 8 for deeper MLP.
__global__ __launch_bounds__(256) void linear_kernel(
    const float* __restrict__ w,   // [IDIM, HDIM]
    const float* __restrict__ b,   // [IDIM]
    const float* __restrict__ h,   // [HDIM]
    float* __restrict__ out)       // [IDIM]
{
    __shared__ float4 s_h[HDIM / 4];   // 1250 float4 = 20 KB

    // Cooperative stage of h into smem
    {
        const float4* __restrict__ hv = (const float4*)h;
        for (int i = threadIdx.x; i < HDIM / 4; i += 256)
            s_h[i] = hv[i];
    }
    __syncthreads();

    const int row  = blockIdx.x * 8 + (threadIdx.x >> 5);
    const int lane = threadIdx.x & 31;
    if (row >= IDIM) return;

    const float4* __restrict__ wr = (const float4*)(w + (size_t)row * HDIM);

    float acc = 0.0f;
    #pragma unroll 8
    for (int v = lane; v < HDIM / 4; v += 32) {
        float4 a = ldcs4(wr + v);
        float4 c = s_h[v];
        acc += a.x * c.x + a.y * c.y + a.z * c.z + a.w * c.w;
    }
    acc = warp_reduce(acc);
    if (lane == 0) out[row] = acc + b[row];
}

extern "C" void kernel_launch(void* const* d_in, const int* in_sizes, int n_in,
                              void* d_out, int out_size)
{
    const float* input = (const float*)d_in[0];   // [1, IDIM]
    const float* w_ih1 = (const float*)d_in[1];   // [4H, IDIM]
    const float* w_hh1 = (const float*)d_in[2];   // [4H, H]
    const float* b_ih1 = (const float*)d_in[3];   // [4H]
    const float* b_hh1 = (const float*)d_in[4];   // [4H]
    const float* w_ih2 = (const float*)d_in[5];   // [4H, H]
    const float* w_hh2 = (const float*)d_in[6];   // [4H, H]
    const float* b_ih2 = (const float*)d_in[7];   // [4H]
    const float* b_hh2 = (const float*)d_in[8];   // [4H]
    const float* w_lin = (const float*)d_in[9];   // [IDIM, H]
    const float* b_lin = (const float*)d_in[10];  // [IDIM]
    const float* h_t   = (const float*)d_in[11];  // [1, H]
    const float* c_t   = (const float*)d_in[12];  // [1, H]
    const float* h2_t  = (const float*)d_in[13];  // [1, H]
    const float* c2_t  = (const float*)d_in[14];  // [1, H]
    float* out = (float*)d_out;

    float* h1;
    float* h2;
    cudaGetSymbolAddress((void**)&h1, g_h1);
    cudaGetSymbolAddress((void**)&h2, g_h2);

    // Prologue: compute all-zero flags for the two persistent hidden states.
    zero_flag_kernel<<<2, 1024>>>(h_t, h2_t);

    // Layer 1: x = input (IDIM), recurrent state h_t (flag 0)
    lstm_cell_kernel<IDIM><<<HDIM, 128>>>(input, w_ih1, w_hh1, b_ih1, b_hh1,
                                          h_t, c_t, h1, 0);
    // Layer 2: x = h1 (HDIM), recurrent state h2_t (flag 1)
    lstm_cell_kernel<HDIM><<<HDIM, 128>>>(h1, w_ih2, w_hh2, b_ih2, b_hh2,
                                          h2_t, c2_t, h2, 1);
    // Output linear
    linear_kernel<<<(IDIM + 7) / 8, 256>>>(w_lin, b_lin, h2, out);
}

// round 10
// speedup vs baseline: 1.0147x; 1.0147x over previous
#include <cuda_runtime.h>
#include <math.h>

#define HDIM 5000
#define IDIM 4000

// Intermediate hidden states + zero-detection flags (device globals)
__device__ float g_h1[HDIM];
__device__ float g_h2[HDIM];
__device__ int   g_nonzero[2];   // [0]: h_t nonzero, [1]: h2_t nonzero

__device__ __forceinline__ float warp_reduce(float v) {
    v += __shfl_down_sync(0xffffffffu, v, 16);
    v += __shfl_down_sync(0xffffffffu, v, 8);
    v += __shfl_down_sync(0xffffffffu, v, 4);
    v += __shfl_down_sync(0xffffffffu, v, 2);
    v += __shfl_down_sync(0xffffffffu, v, 1);
    return v;
}

__device__ __forceinline__ float sigmoidf_(float x) {
    return 1.0f / (1.0f + __expf(-x));
}

// Streaming (evict-first) float4 load for once-read weight data.
__device__ __forceinline__ float4 ldcs4(const float4* p) {
    return __ldcs(p);
}

// Prologue: detect whether each persistent hidden state is entirely zero.
// blockIdx.x = 0 -> h_t, 1 -> h2_t. float4 loads, 1024 threads.
__global__ __launch_bounds__(1024) void zero_flag_kernel(
    const float* __restrict__ ha, const float* __restrict__ hb)
{
    const float* __restrict__ v = (blockIdx.x == 0) ? ha : hb;
    const float4* __restrict__ v4 = (const float4*)v;
    int nz = 0;
    for (int i = threadIdx.x; i < HDIM / 4; i += 1024) {
        float4 a = v4[i];
        nz |= (a.x != 0.0f) | (a.y != 0.0f) | (a.z != 0.0f) | (a.w != 0.0f);
    }
    nz = __syncthreads_or(nz);
    if (threadIdx.x == 0) g_nonzero[blockIdx.x] = nz;
}

// One block per output element j (grid = HDIM). 4 warps; warp g computes the
// full dot product for gate-row g*HDIM + j over [x | h_prev], then thread 0
// applies the LSTM cell elementwise math. The W_hh stream is skipped entirely
// (uniform branch) when the prologue detected h_prev == 0.
// unroll 8 + ldcs: best measured config — DO NOT PERTURB (at ~80% HBM).
template <int NIN>
__global__ __launch_bounds__(128) void lstm_cell_kernel(
    const float* __restrict__ x,       // [NIN]
    const float* __restrict__ w_ih,    // [4H, NIN]
    const float* __restrict__ w_hh,    // [4H, H]
    const float* __restrict__ b_ih,    // [4H]
    const float* __restrict__ b_hh,    // [4H]
    const float* __restrict__ h_prev,  // [H]
    const float* __restrict__ c_prev,  // [H]
    float* __restrict__ h_out,         // [H]
    int flag_idx)
{
    const int j    = blockIdx.x;
    const int wrp  = threadIdx.x >> 5;   // gate index 0..3 (i, f, g, o)
    const int lane = threadIdx.x & 31;
    const int row  = wrp * HDIM + j;

    __shared__ float s_gate[4];

    float acc = 0.0f;

    // dot(W_ih[row, :], x)  — weights streamed (evict-first), x cached
    {
        const float4* __restrict__ wr = (const float4*)(w_ih + (size_t)row * NIN);
        const float4* __restrict__ xv = (const float4*)x;
        #pragma unroll 8
        for (int v = lane; v < NIN / 4; v += 32) {
            float4 a = ldcs4(wr + v);
            float4 b = xv[v];
            acc += a.x * b.x + a.y * b.y + a.z * b.z + a.w * b.w;
        }
    }

    // dot(W_hh[row, :], h_prev) — skipped when h_prev is all-zero.
    if (g_nonzero[flag_idx]) {
        const float4* __restrict__ wr = (const float4*)(w_hh + (size_t)row * HDIM);
        const float4* __restrict__ hv = (const float4*)h_prev;
        #pragma unroll 8
        for (int v = lane; v < HDIM / 4; v += 32) {
            float4 a = ldcs4(wr + v);
            float4 b = hv[v];
            acc += a.x * b.x + a.y * b.y + a.z * b.z + a.w * b.w;
        }
    }

    acc = warp_reduce(acc);
    if (lane == 0) {
        s_gate[wrp] = acc + b_ih[row] + b_hh[row];
    }
    __syncthreads();

    if (threadIdx.x == 0) {
        float gi = sigmoidf_(s_gate[0]);
        float gf = sigmoidf_(s_gate[1]);
        float gg = tanhf(s_gate[2]);
        float go = sigmoidf_(s_gate[3]);
        float c_new = gf * c_prev[j] + gi * gg;
        h_out[j] = go * tanhf(c_new);
    }
}

// out[r] = dot(W[r,:], h) + b[r].  ONE warp per block, one row per block,
// grid = IDIM = 4000 blocks. All 27 blocks/SM are co-resident in a single
// wave (under the 32-CTA/SM cap) -> no wave-quantization tail; finest-
// granularity scheduling; no __syncthreads.
__global__ __launch_bounds__(32) void linear_kernel(
    const float* __restrict__ w,   // [IDIM, HDIM]
    const float* __restrict__ b,   // [IDIM]
    const float* __restrict__ h,   // [HDIM]
    float* __restrict__ out)       // [IDIM]
{
    const int row  = blockIdx.x;
    const int lane = threadIdx.x;

    const float4* __restrict__ wr = (const float4*)(w + (size_t)row * HDIM);
    const float4* __restrict__ hv = (const float4*)h;

    float acc = 0.0f;
    #pragma unroll 8
    for (int v = lane; v < HDIM / 4; v += 32) {
        float4 a = ldcs4(wr + v);
        float4 c = hv[v];
        acc += a.x * c.x + a.y * c.y + a.z * c.z + a.w * c.w;
    }
    acc = warp_reduce(acc);
    if (lane == 0) out[row] = acc + b[row];
}

extern "C" void kernel_launch(void* const* d_in, const int* in_sizes, int n_in,
                              void* d_out, int out_size)
{
    const float* input = (const float*)d_in[0];   // [1, IDIM]
    const float* w_ih1 = (const float*)d_in[1];   // [4H, IDIM]
    const float* w_hh1 = (const float*)d_in[2];   // [4H, H]
    const float* b_ih1 = (const float*)d_in[3];   // [4H]
    const float* b_hh1 = (const float*)d_in[4];   // [4H]
    const float* w_ih2 = (const float*)d_in[5];   // [4H, H]
    const float* w_hh2 = (const float*)d_in[6];   // [4H, H]
    const float* b_ih2 = (const float*)d_in[7];   // [4H]
    const float* b_hh2 = (const float*)d_in[8];   // [4H]
    const float* w_lin = (const float*)d_in[9];   // [IDIM, H]
    const float* b_lin = (const float*)d_in[10];  // [IDIM]
    const float* h_t   = (const float*)d_in[11];  // [1, H]
    const float* c_t   = (const float*)d_in[12];  // [1, H]
    const float* h2_t  = (const float*)d_in[13];  // [1, H]
    const float* c2_t  = (const float*)d_in[14];  // [1, H]
    float* out = (float*)d_out;

    float* h1;
    float* h2;
    cudaGetSymbolAddress((void**)&h1, g_h1);
    cudaGetSymbolAddress((void**)&h2, g_h2);

    // Prologue: compute all-zero flags for the two persistent hidden states.
    zero_flag_kernel<<<2, 1024>>>(h_t, h2_t);

    // Layer 1: x = input (IDIM), recurrent state h_t (flag 0)
    lstm_cell_kernel<IDIM><<<HDIM, 128>>>(input, w_ih1, w_hh1, b_ih1, b_hh1,
                                          h_t, c_t, h1, 0);
    // Layer 2: x = h1 (HDIM), recurrent state h2_t (flag 1)
    lstm_cell_kernel<HDIM><<<HDIM, 128>>>(h1, w_ih2, w_hh2, b_ih2, b_hh2,
                                          h2_t, c2_t, h2, 1);
    // Output linear — single-wave, one warp per row
    linear_kernel<<<IDIM, 32>>>(w_lin, b_lin, h2, out);
}